// round 1
// baseline (speedup 1.0000x reference)
#include <cuda_runtime.h>

// Problem constants (fixed by the reference)
#define BB   4
#define HH   2048
#define WW   2048
#define HW   (HH * WW)          // 4,194,304
#define NVEC (BB * HW / 4)      // 4,194,304 float4's total

__global__ void __launch_bounds__(256, 8) ising_flip_kernel(
    const float* __restrict__ x,       // [B,3,H,W]
    const float* __restrict__ rnd,     // [B,1,H,W]
    const float* __restrict__ drop,    // [H,W]
    float* __restrict__ out)           // [B,3,H,W]
{
    int v = blockIdx.x * blockDim.x + threadIdx.x;   // exact: NVEC threads

    int wv  = v & (WW / 4 - 1);          // vec column 0..511
    int h   = (v >> 9) & (HH - 1);       // row 0..2047
    int b   = v >> 20;                   // batch 0..3

    int col  = wv << 2;
    int row  = h * WW;
    int rowu = ((h - 1) & (HH - 1)) * WW;   // periodic wrap (H power of 2)
    int rowd = ((h + 1) & (HH - 1)) * WW;

    const float* sp = x + (size_t)b * 3 * HW;      // s plane
    const float* tp = sp + HW;                     // tr plane
    const float* bp = sp + 2 * HW;                 // b plane
    const float* rp = rnd + (size_t)b * HW;

    // s center + vertical neighbors (vectorized), horizontal halo (2 scalars)
    float4 c  = *reinterpret_cast<const float4*>(sp + row  + col);
    float4 up = *reinterpret_cast<const float4*>(sp + rowu + col);
    float4 dn = *reinterpret_cast<const float4*>(sp + rowd + col);
    float  lf = sp[row + ((col - 1) & (WW - 1))];   // wrap left of elem 0
    float  rt = sp[row + ((col + 4) & (WW - 1))];   // wrap right of elem 3

    float4 tr = *reinterpret_cast<const float4*>(tp + row + col);
    float4 bv = *reinterpret_cast<const float4*>(bp + row + col);
    float4 rn = *reinterpret_cast<const float4*>(rp + row + col);
    float4 dr = *reinterpret_cast<const float4*>(drop + row + col);

    // neighbor sums (in-register horizontal neighbors)
    float js0 = up.x + dn.x + lf  + c.y;
    float js1 = up.y + dn.y + c.x + c.z;
    float js2 = up.z + dn.z + c.y + c.w;
    float js3 = up.w + dn.w + c.z + rt;

    float4 os, ot;

    #define LANE(i, S, JS, TRv, BVv, RNv, DRv, OS, OT)                        \
    {                                                                          \
        float de = 2.0f * (S) * (JS);                                          \
        float p  = (de <= 0.0f) ? 1.0f : expf(-de * (BVv));                    \
        bool  fl = ((RNv) < p) && ((DRv) > 0.5f);                              \
        OS = fl ? -(S) : (S);                                                  \
        OT = 0.9f * (TRv) + 0.1f * (S);                                        \
    }

    LANE(0, c.x, js0, tr.x, bv.x, rn.x, dr.x, os.x, ot.x)
    LANE(1, c.y, js1, tr.y, bv.y, rn.y, dr.y, os.y, ot.y)
    LANE(2, c.z, js2, tr.z, bv.z, rn.z, dr.z, os.z, ot.z)
    LANE(3, c.w, js3, tr.w, bv.w, rn.w, dr.w, os.w, ot.w)

    #undef LANE

    float* op = out + (size_t)b * 3 * HW;
    *reinterpret_cast<float4*>(op + row + col)          = os;   // s * flip
    *reinterpret_cast<float4*>(op + HW + row + col)     = ot;   // tr_new
    *reinterpret_cast<float4*>(op + 2 * HW + row + col) = bv;   // b passthrough
}

extern "C" void kernel_launch(void* const* d_in, const int* in_sizes, int n_in,
                              void* d_out, int out_size)
{
    const float* x    = (const float*)d_in[0];   // [4,3,2048,2048]
    const float* rnd  = (const float*)d_in[1];   // [4,1,2048,2048]
    const float* drop = (const float*)d_in[2];   // [2048,2048]
    float* out = (float*)d_out;

    dim3 block(256);
    dim3 grid(NVEC / 256);   // 16384 blocks, exact coverage
    ising_flip_kernel<<<grid, block>>>(x, rnd, drop, out);
}

// round 17
// speedup vs baseline: 1.0349x; 1.0349x over previous
#include <cuda_runtime.h>

// Problem constants (fixed by the reference)
#define BB   4
#define HH   2048
#define WW   2048
#define HW   (HH * WW)          // 4,194,304
#define NVEC (BB * HW / 4)      // 4,194,304 float4's total

__global__ void __launch_bounds__(256, 8) ising_flip_kernel(
    const float* __restrict__ x,       // [B,3,H,W]
    const float* __restrict__ rnd,     // [B,1,H,W]
    const float* __restrict__ drop,    // [H,W]
    float* __restrict__ out)           // [B,3,H,W]
{
    int v = blockIdx.x * blockDim.x + threadIdx.x;   // exact: NVEC threads

    int wv  = v & (WW / 4 - 1);          // vec column 0..511
    int h   = (v >> 9) & (HH - 1);       // row 0..2047
    int b   = v >> 20;                   // batch 0..3

    int col  = wv << 2;
    int row  = h * WW;
    int rowu = ((h - 1) & (HH - 1)) * WW;   // periodic wrap (H power of 2)
    int rowd = ((h + 1) & (HH - 1)) * WW;

    const float* sp = x + (size_t)b * 3 * HW;      // s plane   (reused: stencil)
    const float* tp = sp + HW;                     // tr plane  (single-use)
    const float* bp = sp + 2 * HW;                 // b plane   (single-use)
    const float* rp = rnd + (size_t)b * HW;        // rand      (single-use)

    // s center + vertical neighbors: default caching (reused by neighbor blocks)
    float4 c  = *reinterpret_cast<const float4*>(sp + row  + col);
    float4 up = *reinterpret_cast<const float4*>(sp + rowu + col);
    float4 dn = *reinterpret_cast<const float4*>(sp + rowd + col);
    float  lf = sp[row + ((col - 1) & (WW - 1))];   // wrap left of elem 0
    float  rt = sp[row + ((col + 4) & (WW - 1))];   // wrap right of elem 3

    // single-use streams: evict-first so they don't displace s / dropout in L2
    float4 tr = __ldcs(reinterpret_cast<const float4*>(tp + row + col));
    float4 bv = __ldcs(reinterpret_cast<const float4*>(bp + row + col));
    float4 rn = __ldcs(reinterpret_cast<const float4*>(rp + row + col));
    // dropout plane: reused across all 4 batches -> keep cached
    float4 dr = *reinterpret_cast<const float4*>(drop + row + col);

    // neighbor sums (in-register horizontal neighbors)
    float js0 = up.x + dn.x + lf  + c.y;
    float js1 = up.y + dn.y + c.x + c.z;
    float js2 = up.z + dn.z + c.y + c.w;
    float js3 = up.w + dn.w + c.z + rt;

    float4 os, ot;

    #define LANE(S, JS, TRv, BVv, RNv, DRv, OS, OT)                           \
    {                                                                          \
        float de = 2.0f * (S) * (JS);                                          \
        float p  = (de <= 0.0f) ? 1.0f : expf(-de * (BVv));                    \
        bool  fl = ((RNv) < p) && ((DRv) > 0.5f);                              \
        OS = fl ? -(S) : (S);                                                  \
        OT = 0.9f * (TRv) + 0.1f * (S);                                        \
    }

    LANE(c.x, js0, tr.x, bv.x, rn.x, dr.x, os.x, ot.x)
    LANE(c.y, js1, tr.y, bv.y, rn.y, dr.y, os.y, ot.y)
    LANE(c.z, js2, tr.z, bv.z, rn.z, dr.z, os.z, ot.z)
    LANE(c.w, js3, tr.w, bv.w, rn.w, dr.w, os.w, ot.w)

    #undef LANE

    float* op = out + (size_t)b * 3 * HW;
    // write-once outputs: streaming stores (evict-first)
    __stcs(reinterpret_cast<float4*>(op + row + col),          os);  // s * flip
    __stcs(reinterpret_cast<float4*>(op + HW + row + col),     ot);  // tr_new
    __stcs(reinterpret_cast<float4*>(op + 2 * HW + row + col), bv);  // b passthrough
}

extern "C" void kernel_launch(void* const* d_in, const int* in_sizes, int n_in,
                              void* d_out, int out_size)
{
    const float* x    = (const float*)d_in[0];   // [4,3,2048,2048]
    const float* rnd  = (const float*)d_in[1];   // [4,1,2048,2048]
    const float* drop = (const float*)d_in[2];   // [2048,2048]
    float* out = (float*)d_out;

    dim3 block(256);
    dim3 grid(NVEC / 256);   // 16384 blocks, exact coverage
    ising_flip_kernel<<<grid, block>>>(x, rnd, drop, out);
}